// round 2
// baseline (speedup 1.0000x reference)
#include <cuda_runtime.h>
#include <cuda_bf16.h>
#include <cstddef>

// Problem constants
#define B_   8
#define T_   32
#define N_   500
#define DP_  200
#define DC_  128
#define H_   4
#define U_   64

// Scratch (device globals: allocation-free rule)
__device__ float g_S[B_*H_*N_*U_];                 // [b][h][n][u]  src proj   (4.1 MB)
__device__ float g_D[B_*H_*N_*U_];                 // [b][h][m][u]  dst proj   (4.1 MB)
__device__ float g_attn[B_*N_*H_*N_];              // [b][n][h][m]             (32 MB)
__device__ float g_msg[B_*H_*N_*T_*U_];            // [b][h][m][t][u]          (131 MB)

// ---------------------------------------------------------------------------
// Kernel A: projections.  GEMM M=4000 (b*500+n), K=200, Ncols=512
//   col c: mat = c>>8 (0=src,1=dst), h=(c>>6)&3, u=c&63
// 128x128x8 double-buffered SIMT SGEMM.
// ---------------------------------------------------------------------------
__global__ __launch_bounds__(256, 2)
void proj_gemm(const float* __restrict__ prev,
               const float* __restrict__ Wsrc,
               const float* __restrict__ Wdst)
{
    const int rowBase = blockIdx.x * 128;
    const int colBase = blockIdx.y * 128;

    __shared__ float As[2][8][132];
    __shared__ float Bs[2][8][128];

    const int tid  = threadIdx.x;
    const int aRow = tid >> 1;
    const int aK   = (tid & 1) * 4;
    const int bK   = tid >> 5;
    const int bCol = (tid & 31) * 4;
    const int tx   = tid & 15;
    const int ty   = tid >> 4;

    const int gRow  = rowBase + aRow;
    const bool rowOk = gRow < 4000;
    const float* aPtr = prev + (size_t)gRow * DP_ + aK;

    // B element (k=d, c): base + d*64
    const int cB   = colBase + bCol;
    const int matB = cB >> 8;
    const int hB   = (cB >> 6) & 3;
    const int uB   = cB & 63;
    const float* bPtr = (matB ? Wdst : Wsrc) + hB * (DP_*U_) + bK * U_ + uB;

    const int KSTEPS = DP_ / 8;  // 25

    float4 aReg = rowOk ? *(const float4*)aPtr : make_float4(0,0,0,0);
    float4 bReg = *(const float4*)bPtr;

    As[0][aK+0][aRow] = aReg.x; As[0][aK+1][aRow] = aReg.y;
    As[0][aK+2][aRow] = aReg.z; As[0][aK+3][aRow] = aReg.w;
    *(float4*)&Bs[0][bK][bCol] = bReg;
    __syncthreads();

    float acc[2][2][4][4] = {};

    for (int ks = 0; ks < KSTEPS; ks++) {
        const int cur = ks & 1;
        if (ks + 1 < KSTEPS) {
            aReg = rowOk ? *(const float4*)(aPtr + (ks+1)*8) : make_float4(0,0,0,0);
            bReg = *(const float4*)(bPtr + (ks+1)*8*U_);
        }
        #pragma unroll
        for (int kk = 0; kk < 8; kk++) {
            float ar[2][4], br[2][4];
            *(float4*)ar[0] = *(const float4*)&As[cur][kk][ty*4];
            *(float4*)ar[1] = *(const float4*)&As[cur][kk][ty*4 + 64];
            *(float4*)br[0] = *(const float4*)&Bs[cur][kk][tx*4];
            *(float4*)br[1] = *(const float4*)&Bs[cur][kk][tx*4 + 64];
            #pragma unroll
            for (int rg=0; rg<2; rg++)
              #pragma unroll
              for (int cg=0; cg<2; cg++)
                #pragma unroll
                for (int i=0;i<4;i++)
                  #pragma unroll
                  for (int j=0;j<4;j++)
                    acc[rg][cg][i][j] = fmaf(ar[rg][i], br[cg][j], acc[rg][cg][i][j]);
        }
        if (ks + 1 < KSTEPS) {
            const int nxt = cur ^ 1;
            As[nxt][aK+0][aRow] = aReg.x; As[nxt][aK+1][aRow] = aReg.y;
            As[nxt][aK+2][aRow] = aReg.z; As[nxt][aK+3][aRow] = aReg.w;
            *(float4*)&Bs[nxt][bK][bCol] = bReg;
            __syncthreads();
        }
    }

    #pragma unroll
    for (int rg=0; rg<2; rg++) {
        #pragma unroll
        for (int i=0;i<4;i++) {
            const int r = rowBase + ty*4 + rg*64 + i;
            if (r < 4000) {
                const int b = r / N_;
                const int n = r - b * N_;
                #pragma unroll
                for (int cg=0; cg<2; cg++) {
                    const int c = colBase + tx*4 + cg*64;
                    const int mat = c >> 8;
                    const int h   = (c >> 6) & 3;
                    const int u   = c & 63;
                    float* dst = (mat ? g_D : g_S) + ((size_t)(b*H_ + h)*N_ + n)*U_ + u;
                    float4 v = make_float4(acc[rg][cg][i][0], acc[rg][cg][i][1],
                                           acc[rg][cg][i][2], acc[rg][cg][i][3]);
                    *(float4*)dst = v;
                }
            }
        }
    }
}

// ---------------------------------------------------------------------------
// Kernel B: GATv2 scores + softmax.
// Block = (b,h, 16-row n-tile). Full h_dst tile (500x64, padded to 512 rows,
// stride 65 for conflict-free reads) resident in dynamic smem.
// score[n][m] = sum_u a[u] * lrelu(S[n,u] + D[m,u]),  lrelu(t)=max(t, 0.2t)
// Then per-row softmax over m, write attn[b][n][h][m].
// ---------------------------------------------------------------------------
__global__ __launch_bounds__(256)
void score_softmax_kernel(const float* __restrict__ aVec)
{
    extern __shared__ float sh[];
    float* Dsh = sh;                     // 512*65
    float* Ssh = Dsh + 512*65;           // 16*64
    float* aSh = Ssh + 16*64;            // 64 (+64 pad)
    float* sc  = aSh + 128;              // 16*500

    const int bh = blockIdx.y;           // b*4 + h
    const int b  = bh >> 2;
    const int h  = bh & 3;
    const int nBase = blockIdx.x * 16;
    const int tid = threadIdx.x;

    const float* Dg = g_D + (size_t)bh * N_ * U_;
    const float* Sg = g_S + (size_t)bh * N_ * U_;

    for (int idx = tid; idx < 512*16; idx += 256) {
        const int m = idx >> 4;
        const int u = (idx & 15) * 4;
        float4 v = (m < N_) ? *(const float4*)(Dg + m*U_ + u) : make_float4(0,0,0,0);
        float* dst = &Dsh[m*65 + u];
        dst[0]=v.x; dst[1]=v.y; dst[2]=v.z; dst[3]=v.w;
    }
    for (int idx = tid; idx < 16*16; idx += 256) {
        const int r = idx >> 4;
        const int u = (idx & 15) * 4;
        const int n = nBase + r;
        float4 v = (n < N_) ? *(const float4*)(Sg + n*U_ + u) : make_float4(0,0,0,0);
        float* dst = &Ssh[r*U_ + u];
        dst[0]=v.x; dst[1]=v.y; dst[2]=v.z; dst[3]=v.w;
    }
    if (tid < 64) aSh[tid] = aVec[h*U_ + tid];
    __syncthreads();

    // scoring: thread (tx in [0,64), tyy in [0,4)): rows tyy*4+i, cols tx+64k
    const int tx  = tid & 63;
    const int tyy = tid >> 6;

    float acc[4][8];
    #pragma unroll
    for (int i=0;i<4;i++)
        #pragma unroll
        for (int k=0;k<8;k++) acc[i][k]=0.f;

    for (int u = 0; u < U_; u++) {
        const float au = aSh[u];
        float s[4];
        #pragma unroll
        for (int i=0;i<4;i++) s[i] = Ssh[(tyy*4+i)*U_ + u];
        #pragma unroll
        for (int k=0;k<8;k++) {
            const float d = Dsh[(tx + 64*k)*65 + u];
            #pragma unroll
            for (int i=0;i<4;i++) {
                const float t  = s[i] + d;
                const float lr = fmaxf(t, 0.2f * t);
                acc[i][k] = fmaf(au, lr, acc[i][k]);
            }
        }
    }
    #pragma unroll
    for (int i=0;i<4;i++)
        #pragma unroll
        for (int k=0;k<8;k++) {
            const int m = tx + 64*k;
            if (m < N_) sc[(tyy*4+i)*N_ + m] = acc[i][k];
        }
    __syncthreads();

    // softmax: 8 warps x 2 rows
    const int warp = tid >> 5, lane = tid & 31;
    #pragma unroll
    for (int rr = 0; rr < 2; rr++) {
        const int r = warp*2 + rr;
        const int n = nBase + r;
        float mx = -1e30f;
        for (int m = lane; m < N_; m += 32) mx = fmaxf(mx, sc[r*N_+m]);
        #pragma unroll
        for (int o=16;o>0;o>>=1) mx = fmaxf(mx, __shfl_xor_sync(0xffffffffu, mx, o));
        float sum = 0.f;
        for (int m = lane; m < N_; m += 32) {
            const float e = __expf(sc[r*N_+m] - mx);
            sc[r*N_+m] = e;
            sum += e;
        }
        #pragma unroll
        for (int o=16;o>0;o>>=1) sum += __shfl_xor_sync(0xffffffffu, sum, o);
        const float inv = 1.f / sum;
        if (n < N_) {
            float* dst = g_attn + (((size_t)b*N_ + n)*H_ + h)*N_;
            for (int m = lane; m < N_; m += 32) dst[m] = sc[r*N_+m]*inv;
        }
    }
}

// ---------------------------------------------------------------------------
// Kernel C: msg GEMM. M=128000 (r = (b*32+t)*500+m), K=128, Ncols=256 (h,u).
// Output scattered to g_msg[b][h][m][t][u].
// ---------------------------------------------------------------------------
__global__ __launch_bounds__(256, 2)
void msg_gemm(const float* __restrict__ curr,
              const float* __restrict__ Wmsg)
{
    const int rowBase = blockIdx.x * 128;
    const int colBase = blockIdx.y * 128;

    __shared__ float As[2][8][132];
    __shared__ float Bs[2][8][128];

    const int tid  = threadIdx.x;
    const int aRow = tid >> 1;
    const int aK   = (tid & 1) * 4;
    const int bK   = tid >> 5;
    const int bCol = (tid & 31) * 4;
    const int tx   = tid & 15;
    const int ty   = tid >> 4;

    const float* aPtr = curr + (size_t)(rowBase + aRow) * DC_ + aK;

    const int cB = colBase + bCol;
    const int hB = cB >> 6;
    const int uB = cB & 63;
    const float* bPtr = Wmsg + hB * (DC_*U_) + bK * U_ + uB;

    const int KSTEPS = DC_ / 8;  // 16

    float4 aReg = *(const float4*)aPtr;
    float4 bReg = *(const float4*)bPtr;

    As[0][aK+0][aRow] = aReg.x; As[0][aK+1][aRow] = aReg.y;
    As[0][aK+2][aRow] = aReg.z; As[0][aK+3][aRow] = aReg.w;
    *(float4*)&Bs[0][bK][bCol] = bReg;
    __syncthreads();

    float acc[2][2][4][4] = {};

    for (int ks = 0; ks < KSTEPS; ks++) {
        const int cur = ks & 1;
        if (ks + 1 < KSTEPS) {
            aReg = *(const float4*)(aPtr + (ks+1)*8);
            bReg = *(const float4*)(bPtr + (ks+1)*8*U_);
        }
        #pragma unroll
        for (int kk = 0; kk < 8; kk++) {
            float ar[2][4], br[2][4];
            *(float4*)ar[0] = *(const float4*)&As[cur][kk][ty*4];
            *(float4*)ar[1] = *(const float4*)&As[cur][kk][ty*4 + 64];
            *(float4*)br[0] = *(const float4*)&Bs[cur][kk][tx*4];
            *(float4*)br[1] = *(const float4*)&Bs[cur][kk][tx*4 + 64];
            #pragma unroll
            for (int rg=0; rg<2; rg++)
              #pragma unroll
              for (int cg=0; cg<2; cg++)
                #pragma unroll
                for (int i=0;i<4;i++)
                  #pragma unroll
                  for (int j=0;j<4;j++)
                    acc[rg][cg][i][j] = fmaf(ar[rg][i], br[cg][j], acc[rg][cg][i][j]);
        }
        if (ks + 1 < KSTEPS) {
            const int nxt = cur ^ 1;
            As[nxt][aK+0][aRow] = aReg.x; As[nxt][aK+1][aRow] = aReg.y;
            As[nxt][aK+2][aRow] = aReg.z; As[nxt][aK+3][aRow] = aReg.w;
            *(float4*)&Bs[nxt][bK][bCol] = bReg;
            __syncthreads();
        }
    }

    #pragma unroll
    for (int rg=0; rg<2; rg++) {
        #pragma unroll
        for (int i=0;i<4;i++) {
            const int r = rowBase + ty*4 + rg*64 + i;   // always < 128000
            const int b = r / (T_*N_);
            const int rem = r - b*(T_*N_);
            const int t = rem / N_;
            const int m = rem - t*N_;
            #pragma unroll
            for (int cg=0; cg<2; cg++) {
                const int c = colBase + tx*4 + cg*64;
                const int h = c >> 6;
                const int u = c & 63;
                float* dst = g_msg + ((((size_t)(b*H_ + h)*N_ + m)*T_ + t)*U_ + u);
                float4 v = make_float4(acc[rg][cg][i][0], acc[rg][cg][i][1],
                                       acc[rg][cg][i][2], acc[rg][cg][i][3]);
                *(float4*)dst = v;
            }
        }
    }
}

// ---------------------------------------------------------------------------
// Kernel D: mix GEMM per batch b (blockIdx.z):
//   O[n][t*64+u] = sum_{h,m} attn[b][n][h*500+m] * msg[b][h*500+m][t*64+u]
//   out[b][t][n][u] = 0.25 * O[n][t*64+u]
// M=500, Ncols=2048, K=2000.
// ---------------------------------------------------------------------------
__global__ __launch_bounds__(256, 2)
void mix_gemm(float* __restrict__ out)
{
    const int b = blockIdx.z;
    const int rowBase = blockIdx.x * 128;
    const int colBase = blockIdx.y * 128;

    const float* A  = g_attn + (size_t)b * N_ * (H_*N_);       // [500 x 2000]
    const float* Bm = g_msg  + (size_t)b * (H_*N_) * (T_*U_);  // [2000 x 2048]

    __shared__ float As[2][8][132];
    __shared__ float Bs[2][8][128];

    const int tid  = threadIdx.x;
    const int aRow = tid >> 1;
    const int aK   = (tid & 1) * 4;
    const int bK   = tid >> 5;
    const int bCol = (tid & 31) * 4;
    const int tx   = tid & 15;
    const int ty   = tid >> 4;

    const int gRow  = rowBase + aRow;
    const bool rowOk = gRow < N_;
    const float* aPtr = A + (size_t)gRow * (H_*N_) + aK;
    const float* bPtr = Bm + (size_t)bK * (T_*U_) + colBase + bCol;

    const int KSTEPS = (H_*N_) / 8;  // 250

    float4 aReg = rowOk ? *(const float4*)aPtr : make_float4(0,0,0,0);
    float4 bReg = *(const float4*)bPtr;

    As[0][aK+0][aRow] = aReg.x; As[0][aK+1][aRow] = aReg.y;
    As[0][aK+2][aRow] = aReg.z; As[0][aK+3][aRow] = aReg.w;
    *(float4*)&Bs[0][bK][bCol] = bReg;
    __syncthreads();

    float acc[2][2][4][4] = {};

    for (int ks = 0; ks < KSTEPS; ks++) {
        const int cur = ks & 1;
        if (ks + 1 < KSTEPS) {
            aReg = rowOk ? *(const float4*)(aPtr + (ks+1)*8) : make_float4(0,0,0,0);
            bReg = *(const float4*)(bPtr + (size_t)(ks+1)*8*(T_*U_));
        }
        #pragma unroll
        for (int kk = 0; kk < 8; kk++) {
            float ar[2][4], br[2][4];
            *(float4*)ar[0] = *(const float4*)&As[cur][kk][ty*4];
            *(float4*)ar[1] = *(const float4*)&As[cur][kk][ty*4 + 64];
            *(float4*)br[0] = *(const float4*)&Bs[cur][kk][tx*4];
            *(float4*)br[1] = *(const float4*)&Bs[cur][kk][tx*4 + 64];
            #pragma unroll
            for (int rg=0; rg<2; rg++)
              #pragma unroll
              for (int cg=0; cg<2; cg++)
                #pragma unroll
                for (int i=0;i<4;i++)
                  #pragma unroll
                  for (int j=0;j<4;j++)
                    acc[rg][cg][i][j] = fmaf(ar[rg][i], br[cg][j], acc[rg][cg][i][j]);
        }
        if (ks + 1 < KSTEPS) {
            const int nxt = cur ^ 1;
            As[nxt][aK+0][aRow] = aReg.x; As[nxt][aK+1][aRow] = aReg.y;
            As[nxt][aK+2][aRow] = aReg.z; As[nxt][aK+3][aRow] = aReg.w;
            *(float4*)&Bs[nxt][bK][bCol] = bReg;
            __syncthreads();
        }
    }

    #pragma unroll
    for (int rg=0; rg<2; rg++) {
        #pragma unroll
        for (int i=0;i<4;i++) {
            const int n = rowBase + ty*4 + rg*64 + i;
            if (n < N_) {
                #pragma unroll
                for (int cg=0; cg<2; cg++) {
                    const int c = colBase + tx*4 + cg*64;
                    const int t = c >> 6;
                    const int u = c & 63;
                    float4 v = make_float4(acc[rg][cg][i][0]*0.25f, acc[rg][cg][i][1]*0.25f,
                                           acc[rg][cg][i][2]*0.25f, acc[rg][cg][i][3]*0.25f);
                    *(float4*)&out[(((size_t)b*T_ + t)*N_ + n)*U_ + u] = v;
                }
            }
        }
    }
}

// ---------------------------------------------------------------------------
extern "C" void kernel_launch(void* const* d_in, const int* in_sizes, int n_in,
                              void* d_out, int out_size)
{
    const float* prev = (const float*)d_in[0];   // [8,500,200]
    const float* curr = (const float*)d_in[1];   // [8,32,500,128]
    const float* Wsrc = (const float*)d_in[2];   // [4,200,64]
    const float* Wdst = (const float*)d_in[3];   // [4,200,64]
    const float* aV   = (const float*)d_in[4];   // [4,64,1]
    const float* Wmsg = (const float*)d_in[5];   // [4,128,64]
    float* out = (float*)d_out;                  // [8,32,500,64]

    // A: projections  (M=4000, N=512, K=200)
    proj_gemm<<<dim3(32, 4), 256>>>(prev, Wsrc, Wdst);

    // B: scores + softmax
    const size_t shB = (size_t)(512*65 + 16*64 + 128 + 16*500) * sizeof(float);
    cudaFuncSetAttribute(score_softmax_kernel,
                         cudaFuncAttributeMaxDynamicSharedMemorySize, (int)shB);
    score_softmax_kernel<<<dim3(32, 32), 256, shB>>>(aV);

    // C: msg GEMM  (M=128000, N=256, K=128)
    msg_gemm<<<dim3(1000, 2), 256>>>(curr, Wmsg);

    // D: mix GEMM  (per batch: M=500, N=2048, K=2000)
    mix_gemm<<<dim3(4, 16, 8), 256>>>(out);
}